// round 15
// baseline (speedup 1.0000x reference)
#include <cuda_runtime.h>
#include <cuda_bf16.h>
#include <cuda_fp8.h>
#include <math.h>
#include <stdint.h>

// Problem shape (fixed): B=4096, D=512, N=2B=8192, T=0.1
#define BHALF 4096
#define NROWS 8192
#define DDIM  512
#define INV_T 10.0f
#define MSHIFT 10.0f
#define QS    16.0f                 // quantization scale: q = e4m3(16*z)
#define EPSC  (10.0f / 256.0f)      // logit = acc * 10 / QS^2
#define NBLK 64                     // 64 row blocks of 128
#define NTILES 2080                 // upper-triangle tiles
#define NCTA 148                    // one CTA per SM (all co-resident)
#define NSTB 4                      // B ring stages
#define CPT 4                       // chunks per tile (fp8: 4 x 128B of K)
#define NTHR 512                    // 16 warps: 4 per SMSP

// Scratch (__device__ globals: allocation-free rule)
__device__ uint8_t g_zq[NROWS * DDIM];            // e4m3(16 * zhat), 4.2 MB
__device__ float   g_pos[BHALF];                  // positive logits (fp32)
__device__ float   g_diag[NROWS];                 // exp(diag logit - 10)
__device__ float   g_rowtile[NTILES * 128];       // per-tile row sums (strip-major)
__device__ float   g_coltile[NTILES * 128];       // per-tile col sums (i<j)
__device__ float   g_bsum[NBLK];                  // per-row-block loss sums
__device__ unsigned long long g_arrive;           // monotonic barrier counter

// ---------------- helpers ----------------
__device__ __forceinline__ uint32_t smem_u32(const void* p) {
    uint32_t a;
    asm("{ .reg .u64 t; cvta.to.shared.u64 t, %1; cvt.u32.u64 %0, t; }" : "=r"(a) : "l"(p));
    return a;
}
__device__ __forceinline__ void cpasync16(uint32_t dst, const void* src) {
    asm volatile("cp.async.cg.shared.global [%0], [%1], 16;" :: "r"(dst), "l"(src) : "memory");
}
#define CP_COMMIT() asm volatile("cp.async.commit_group;" ::: "memory")
#define CP_WAIT2()  asm volatile("cp.async.wait_group 2;" ::: "memory")
#define CP_WAIT0()  asm volatile("cp.async.wait_group 0;" ::: "memory")

#define LDSM_X4(r, addr) \
    asm volatile("ldmatrix.sync.aligned.m8n8.x4.shared.b16 {%0,%1,%2,%3}, [%4];" \
        : "=r"((r)[0]), "=r"((r)[1]), "=r"((r)[2]), "=r"((r)[3]) : "r"(addr))

#define MMA16832F8(c, a0, a1, a2, a3, b0, b1) \
    asm volatile("mma.sync.aligned.m16n8k32.row.col.f32.e4m3.e4m3.f32 " \
        "{%0,%1,%2,%3}, {%4,%5,%6,%7}, {%8,%9}, {%0,%1,%2,%3};" \
        : "+f"((c)[0]), "+f"((c)[1]), "+f"((c)[2]), "+f"((c)[3]) \
        : "r"(a0), "r"(a1), "r"(a2), "r"(a3), "r"(b0), "r"(b1))

// canonical strip-major tile index for storage (i <= j)
__device__ __forceinline__ int tile_index(int i, int j) {
    return i * (129 - i) / 2 + (j - i);
}

// grid-wide barrier: monotonic counter, graph-replay safe (no reset).
// All NCTA CTAs co-resident (1/SM) -> spin cannot deadlock. (R10-verified.)
__device__ __forceinline__ void grid_barrier() {
    __syncthreads();
    if (threadIdx.x == 0) {
        __threadfence();
        unsigned long long r = atomicAdd(&g_arrive, 1ULL);
        unsigned long long target = (r / NCTA + 1ULL) * NCTA;
        unsigned long long cur;
        do {
            asm volatile("ld.global.cg.u64 %0, [%1];" : "=l"(cur) : "l"(&g_arrive));
            if (cur < target) __nanosleep(64);
        } while (cur < target);
        __threadfence();
    }
    __syncthreads();
}

__device__ __forceinline__ float wred(float v) {
    #pragma unroll
    for (int o = 16; o > 0; o >>= 1) v += __shfl_xor_sync(0xffffffffu, v, o);
    return v;
}

// ---------------------------------------------------------------------------
// Kernel 1: warp-per-pair normalize + quantize + positives + diag correction.
//   grid = 512 blocks x 256 threads (8 warps/block, warp w -> pair).
//   All reductions are shuffle-only: no smem, no __syncthreads.
// ---------------------------------------------------------------------------
__global__ void ntx_norm_pair(const float* __restrict__ zi,
                              const float* __restrict__ zj) {
    const int l = threadIdx.x & 31;
    const int p = blockIdx.x * 8 + (threadIdx.x >> 5);   // 0..4095
    const float4* ra = (const float4*)(zi + (size_t)p * DDIM);
    const float4* rb = (const float4*)(zj + (size_t)p * DDIM);

    float4 a[4], b[4];
    float ssa = 0.0f, ssb = 0.0f, dab = 0.0f;
    #pragma unroll
    for (int c = 0; c < 4; c++) {
        a[c] = ra[l + 32 * c];
        b[c] = rb[l + 32 * c];
        ssa += a[c].x*a[c].x + a[c].y*a[c].y + a[c].z*a[c].z + a[c].w*a[c].w;
        ssb += b[c].x*b[c].x + b[c].y*b[c].y + b[c].z*b[c].z + b[c].w*b[c].w;
        dab += a[c].x*b[c].x + a[c].y*b[c].y + a[c].z*b[c].z + a[c].w*b[c].w;
    }
    ssa = wred(ssa); ssb = wred(ssb); dab = wred(dab);
    const float sa = 1.0f / fmaxf(sqrtf(ssa), 1e-12f);
    const float sb = 1.0f / fmaxf(sqrtf(ssb), 1e-12f);

    uint32_t* wa = (uint32_t*)(g_zq + (size_t)p * DDIM);
    uint32_t* wb = (uint32_t*)(g_zq + (size_t)(p + BHALF) * DDIM);
    float qa = 0.0f, qb = 0.0f;
    #pragma unroll
    for (int c = 0; c < 4; c++) {
        float fa[4] = { a[c].x*sa*QS, a[c].y*sa*QS, a[c].z*sa*QS, a[c].w*sa*QS };
        float fb[4] = { b[c].x*sb*QS, b[c].y*sb*QS, b[c].z*sb*QS, b[c].w*sb*QS };
        uint32_t pka = 0, pkb = 0;
        #pragma unroll
        for (int e = 0; e < 4; e++) {
            __nv_fp8_e4m3 ea(fa[e]);
            __nv_fp8_e4m3 eb(fb[e]);
            float da = float(ea), db = float(eb);
            qa += da * da;  qb += db * db;
            pka |= (uint32_t)ea.__x << (8 * e);
            pkb |= (uint32_t)eb.__x << (8 * e);
        }
        wa[l + 32 * c] = pka;
        wb[l + 32 * c] = pkb;
    }
    qa = wred(qa); qb = wred(qb);
    if (l == 0) {
        g_pos[p] = dab * sa * sb * INV_T;
        g_diag[p]         = expf(fmaf(qa, EPSC, -MSHIFT));
        g_diag[p + BHALF] = expf(fmaf(qb, EPSC, -MSHIFT));
    }
}

// ---------------------------------------------------------------------------
// Kernel 2: symmetric fp8 mma.sync GEMM (R11-verified mainloop) + fused
//   loss/mean tail via grid barrier. 148 CTAs x 512 threads.
// ---------------------------------------------------------------------------
__global__ __launch_bounds__(NTHR, 1) void ntx_gemm_sym(float* __restrict__ out) {
    extern __shared__ char smraw[];
    char* sm = (char*)(((uintptr_t)smraw + 1023) & ~(uintptr_t)1023);
    const uint32_t sbase = smem_u32(sm);
    const uint32_t A0  = sbase;                       // 4 x 16KB = 64 KB
    const uint32_t Bst = sbase + 65536;               // 4 x 16KB = 64 KB
    float* red    = (float*)(sm + 131072);            // 512 floats
    float* colred = (float*)(sm + 131072 + 2048);     // 512 floats (4 wm slices)

    const int tid = threadIdx.x;
    const int l   = tid & 31;
    const int wid = tid >> 5;                // 0..15
    const int wm  = wid >> 2;                // 0..3 row quarter (32 rows)
    const int wn  = wid & 3;                 // 0..3 col quarter (32 cols)
    const int cta = blockIdx.x;
    const int u0  = (cta * NTILES) / NCTA;
    const int u1  = ((cta + 1) * NTILES) / NCTA;

    // per-lane ldmatrix bases
    const uint32_t lx    = (uint32_t)(l & 7);
    const uint32_t a_k16 = (uint32_t)(l >> 4);
    const uint32_t a_row = (uint32_t)(wm * 32 + ((l >> 3) & 1) * 8 + (l & 7));
    uint32_t a_base[2];
    #pragma unroll
    for (int mt = 0; mt < 2; mt++) a_base[mt] = A0 + (a_row + mt * 16) * 128u;
    const uint32_t b_k16 = (uint32_t)((l >> 3) & 1);
    const uint32_t b_row = (uint32_t)(wn * 32 + ((l >> 4) & 1) * 8 + (l & 7));
    uint32_t b_off[2];
    #pragma unroll
    for (int pp = 0; pp < 2; pp++) b_off[pp] = (b_row + pp * 16) * 128u;

    float acc[2][4][4];
    #pragma unroll
    for (int mt = 0; mt < 2; mt++)
        #pragma unroll
        for (int nt = 0; nt < 4; nt++)
            #pragma unroll
            for (int c = 0; c < 4; c++) acc[mt][nt][c] = 0.0f;

    int u = u0;
    while (u < u1) {
        // decode pair-major position u -> strip i, start col j0, seg end
        const int k = u / 65;
        const int v = u - k * 65;
        const int lng = NBLK - k;
        int i, j0, segend;
        if (v < lng) { i = k;            j0 = k + v;         segend = k * 65 + lng; }
        else         { i = NBLK - 1 - k; j0 = i + (v - lng); segend = (k + 1) * 65; }
        if (segend > u1) segend = u1;
        const int nch = (segend - u) * CPT;

        // drain ring, then load A tile for strip i (64KB)
        CP_WAIT0();
        __syncthreads();
        {
            const int r  = tid >> 2;             // 0..127
            const int hh = tid & 3;
            const char* src = (const char*)(g_zq + (size_t)(i * 128 + r) * DDIM);
            #pragma unroll
            for (int kc = 0; kc < CPT; kc++) {
                #pragma unroll
                for (int qq = 0; qq < 2; qq++) {
                    const int cidx = hh * 2 + qq;
                    uint32_t dst = A0 + kc * 16384u + (uint32_t)r * 128u
                                 + (uint32_t)((cidx ^ (r & 7)) << 4);
                    cpasync16(dst, src + kc * 128 + cidx * 16);
                }
            }
            CP_COMMIT();
        }

        auto loadB = [&](int c, int stage) {
            const int tj = j0 + (c >> 2);
            const int kc = c & 3;
            const int r  = tid >> 2;
            const int hh = tid & 3;
            const char* src = (const char*)
                (g_zq + (size_t)(tj * 128 + r) * DDIM) + kc * 128;
            const uint32_t db = Bst + (uint32_t)stage * 16384u + (uint32_t)r * 128u;
            #pragma unroll
            for (int qq = 0; qq < 2; qq++) {
                const int cidx = hh * 2 + qq;
                cpasync16(db + (uint32_t)((cidx ^ (r & 7)) << 4), src + cidx * 16);
            }
        };
        loadB(0, 0); CP_COMMIT();
        if (nch > 1) loadB(1, 1); CP_COMMIT();
        if (nch > 2) loadB(2, 2); CP_COMMIT();

        for (int g = 0; g < nch; g++) {
            CP_WAIT2();
            __syncthreads();
            if (g + 3 < nch) loadB(g + 3, (g + 3) & (NSTB - 1));
            CP_COMMIT();

            const int kc = g & 3;
            const uint32_t Akc = (uint32_t)kc * 16384u;
            const uint32_t Bs  = Bst + (uint32_t)(g & (NSTB - 1)) * 16384u;

            #pragma unroll
            for (int ks = 0; ks < 4; ks++) {      // 4 x k32 per 128B chunk
                const uint32_t aoffs = (((uint32_t)(ks * 2) + a_k16) ^ lx) << 4;
                const uint32_t boffs = (((uint32_t)(ks * 2) + b_k16) ^ lx) << 4;
                uint32_t a[2][4], b[2][4];
                #pragma unroll
                for (int mt = 0; mt < 2; mt++)
                    LDSM_X4(a[mt], a_base[mt] + Akc + aoffs);
                #pragma unroll
                for (int pp = 0; pp < 2; pp++)
                    LDSM_X4(b[pp], Bs + b_off[pp] + boffs);
                #pragma unroll
                for (int mt = 0; mt < 2; mt++) {
                    #pragma unroll
                    for (int pp = 0; pp < 2; pp++) {
                        MMA16832F8(acc[mt][pp*2+0], a[mt][0], a[mt][1], a[mt][2], a[mt][3],
                                   b[pp][0], b[pp][1]);
                        MMA16832F8(acc[mt][pp*2+1], a[mt][0], a[mt][1], a[mt][2], a[mt][3],
                                   b[pp][2], b[pp][3]);
                    }
                }
            }

            if (kc == CPT - 1) {
                const int j  = j0 + (g >> 2);
                const int tl = tile_index(i, j);
                float rac[2][2], cs[4][2];
                #pragma unroll
                for (int x = 0; x < 2; x++) { rac[x][0] = 0.0f; rac[x][1] = 0.0f; }
                #pragma unroll
                for (int x = 0; x < 4; x++) { cs[x][0] = 0.0f;  cs[x][1] = 0.0f; }
                #pragma unroll
                for (int mt = 0; mt < 2; mt++) {
                    #pragma unroll
                    for (int nt = 0; nt < 4; nt++) {
                        float e0 = __expf(fmaf(acc[mt][nt][0], EPSC, -MSHIFT));
                        float e1 = __expf(fmaf(acc[mt][nt][1], EPSC, -MSHIFT));
                        float e2 = __expf(fmaf(acc[mt][nt][2], EPSC, -MSHIFT));
                        float e3 = __expf(fmaf(acc[mt][nt][3], EPSC, -MSHIFT));
                        rac[mt][0] += e0 + e1;
                        rac[mt][1] += e2 + e3;
                        cs[nt][0]  += e0 + e2;
                        cs[nt][1]  += e1 + e3;
                        acc[mt][nt][0] = 0.0f; acc[mt][nt][1] = 0.0f;
                        acc[mt][nt][2] = 0.0f; acc[mt][nt][3] = 0.0f;
                    }
                }
                // row reduce: lanes sharing a row (strides 1,2)
                #pragma unroll
                for (int mt = 0; mt < 2; mt++) {
                    #pragma unroll
                    for (int h = 0; h < 2; h++) {
                        float vv = rac[mt][h];
                        vv += __shfl_xor_sync(0xffffffffu, vv, 1);
                        vv += __shfl_xor_sync(0xffffffffu, vv, 2);
                        if ((l & 3) == 0) {
                            const int row_local = wm * 32 + mt * 16 + (l >> 2) + 8 * h;
                            red[row_local * 4 + wn] = vv;
                        }
                    }
                }
                // col reduce across 8 row-lane groups (strides 4,8,16)
                #pragma unroll
                for (int off = 4; off <= 16; off <<= 1)
                    #pragma unroll
                    for (int nt = 0; nt < 4; nt++) {
                        cs[nt][0] += __shfl_xor_sync(0xffffffffu, cs[nt][0], off);
                        cs[nt][1] += __shfl_xor_sync(0xffffffffu, cs[nt][1], off);
                    }
                if (l < 4) {
                    #pragma unroll
                    for (int nt = 0; nt < 4; nt++) {
                        const int colb = wn * 32 + (nt >> 1) * 16 + (nt & 1) * 8 + 2 * l;
                        colred[wm * 128 + colb    ] = cs[nt][0];
                        colred[wm * 128 + colb + 1] = cs[nt][1];
                    }
                }
                __syncthreads();
                if (tid < 128) {
                    g_rowtile[(size_t)tl * 128 + tid] =
                        red[tid*4+0] + red[tid*4+1] + red[tid*4+2] + red[tid*4+3];
                    if (j > i)
                        g_coltile[(size_t)tl * 128 + tid] =
                            colred[tid] + colred[128 + tid] +
                            colred[256 + tid] + colred[384 + tid];
                }
            }
        }
        u = segend;
    }

    // ============ fused tail: per-row loss -> per-block sums -> mean ========
    grid_barrier();
    if (cta < NBLK) {
        const int b = cta;
        float loss = 0.0f;
        if (tid < 128) {
            const int rl = tid;
            const int r  = b * 128 + rl;
            const int base_b = b * (129 - b) / 2;
            float s = 0.0f;
            for (int j = b; j < NBLK; j++)
                s += g_rowtile[(size_t)(base_b + (j - b)) * 128 + rl];
            for (int i2 = 0; i2 < b; i2++)
                s += g_coltile[(size_t)(i2 * (129 - i2) / 2 + (b - i2)) * 128 + rl];
            const float pos = g_pos[r & (BHALF - 1)];
            loss = MSHIFT + logf(s - g_diag[r]) - pos;
        }
        loss = wred(loss);
        if ((tid & 31) == 0) red[tid >> 5] = loss;
        __syncthreads();
        if (tid == 0) g_bsum[b] = red[0] + red[1] + red[2] + red[3];
    }
    grid_barrier();
    if (cta == 0 && tid < 64) {
        float s = g_bsum[tid];
        #pragma unroll
        for (int o = 16; o > 0; o >>= 1) s += __shfl_xor_sync(0xffffffffu, s, o);
        if (tid == 0)  red[0] = s;
        if (tid == 32) red[1] = s;
        __syncwarp();
        if (tid == 0) out[0] = (red[0] + red[1]) * (1.0f / (float)NROWS);
    }
}

// ---------------------------------------------------------------------------
#define SMEM_BYTES (1024 + 65536 + 65536 + 2048 + 2048)

extern "C" void kernel_launch(void* const* d_in, const int* in_sizes, int n_in,
                              void* d_out, int out_size) {
    const float* zi = (const float*)d_in[0];
    const float* zj = (const float*)d_in[1];
    float* out = (float*)d_out;
    (void)in_sizes; (void)n_in; (void)out_size;

    cudaFuncSetAttribute(ntx_gemm_sym,
                         cudaFuncAttributeMaxDynamicSharedMemorySize, SMEM_BYTES);

    ntx_norm_pair<<<512, 256>>>(zi, zj);
    ntx_gemm_sym<<<NCTA, NTHR, SMEM_BYTES>>>(out);
}

// round 16
// speedup vs baseline: 1.0480x; 1.0480x over previous
#include <cuda_runtime.h>
#include <cuda_bf16.h>
#include <cuda_fp8.h>
#include <math.h>
#include <stdint.h>

// Problem shape (fixed): B=4096, D=512, N=2B=8192, T=0.1
#define BHALF 4096
#define NROWS 8192
#define DDIM  512
#define INV_T 10.0f
#define MSHIFT 10.0f
#define QS    16.0f                 // quantization scale: q = e4m3(16*z)
#define EPSC  (10.0f / 256.0f)      // logit = acc * 10 / QS^2
#define NBLK 64                     // 64 row blocks of 128
#define NTILES 2080                 // upper-triangle tiles
#define NCTA 148                    // one CTA per SM
#define NSTB 4                      // B ring stages
#define CPT 4                       // chunks per tile (fp8: 4 x 128B of K)
#define NTHR 512                    // 16 warps: 4 per SMSP

// Scratch (__device__ globals: allocation-free rule)
__device__ uint8_t g_zq[NROWS * DDIM];            // e4m3(16 * zhat), 4.2 MB
__device__ float   g_pos[BHALF];                  // positive logits (fp32)
__device__ float   g_diag[NROWS];                 // exp(diag logit - 10)
__device__ float   g_rowtile[NTILES * 128];       // per-tile row sums (strip-major)
__device__ float   g_coltile[NTILES * 128];       // per-tile col sums (i<j)
__device__ float   g_rowloss[NROWS];

// ---------------- helpers ----------------
__device__ __forceinline__ uint32_t smem_u32(const void* p) {
    uint32_t a;
    asm("{ .reg .u64 t; cvta.to.shared.u64 t, %1; cvt.u32.u64 %0, t; }" : "=r"(a) : "l"(p));
    return a;
}
__device__ __forceinline__ void cpasync16(uint32_t dst, const void* src) {
    asm volatile("cp.async.cg.shared.global [%0], [%1], 16;" :: "r"(dst), "l"(src) : "memory");
}
#define CP_COMMIT() asm volatile("cp.async.commit_group;" ::: "memory")
#define CP_WAIT2()  asm volatile("cp.async.wait_group 2;" ::: "memory")
#define CP_WAIT0()  asm volatile("cp.async.wait_group 0;" ::: "memory")

#define LDSM_X4(r, addr) \
    asm volatile("ldmatrix.sync.aligned.m8n8.x4.shared.b16 {%0,%1,%2,%3}, [%4];" \
        : "=r"((r)[0]), "=r"((r)[1]), "=r"((r)[2]), "=r"((r)[3]) : "r"(addr))

#define MMA16832F8(c, a0, a1, a2, a3, b0, b1) \
    asm volatile("mma.sync.aligned.m16n8k32.row.col.f32.e4m3.e4m3.f32 " \
        "{%0,%1,%2,%3}, {%4,%5,%6,%7}, {%8,%9}, {%0,%1,%2,%3};" \
        : "+f"((c)[0]), "+f"((c)[1]), "+f"((c)[2]), "+f"((c)[3]) \
        : "r"(a0), "r"(a1), "r"(a2), "r"(a3), "r"(b0), "r"(b1))

// canonical strip-major tile index for storage (i <= j)
__device__ __forceinline__ int tile_index(int i, int j) {
    return i * (129 - i) / 2 + (j - i);
}

__device__ __forceinline__ float wred(float v) {
    #pragma unroll
    for (int o = 16; o > 0; o >>= 1) v += __shfl_xor_sync(0xffffffffu, v, o);
    return v;
}

// ---------------------------------------------------------------------------
// Kernel 1: warp-per-pair normalize + quantize + positives + diag correction.
//   grid = 512 blocks x 256 threads (8 warps/block, warp -> pair).
//   Shuffle-only reductions: no smem, no __syncthreads.
// ---------------------------------------------------------------------------
__global__ void ntx_norm_pair(const float* __restrict__ zi,
                              const float* __restrict__ zj) {
    const int l = threadIdx.x & 31;
    const int p = blockIdx.x * 8 + (threadIdx.x >> 5);   // 0..4095
    const float4* ra = (const float4*)(zi + (size_t)p * DDIM);
    const float4* rb = (const float4*)(zj + (size_t)p * DDIM);

    float4 a[4], b[4];
    float ssa = 0.0f, ssb = 0.0f, dab = 0.0f;
    #pragma unroll
    for (int c = 0; c < 4; c++) {
        a[c] = ra[l + 32 * c];
        b[c] = rb[l + 32 * c];
        ssa += a[c].x*a[c].x + a[c].y*a[c].y + a[c].z*a[c].z + a[c].w*a[c].w;
        ssb += b[c].x*b[c].x + b[c].y*b[c].y + b[c].z*b[c].z + b[c].w*b[c].w;
        dab += a[c].x*b[c].x + a[c].y*b[c].y + a[c].z*b[c].z + a[c].w*b[c].w;
    }
    ssa = wred(ssa); ssb = wred(ssb); dab = wred(dab);
    const float sa = 1.0f / fmaxf(sqrtf(ssa), 1e-12f);
    const float sb = 1.0f / fmaxf(sqrtf(ssb), 1e-12f);

    uint32_t* wa = (uint32_t*)(g_zq + (size_t)p * DDIM);
    uint32_t* wb = (uint32_t*)(g_zq + (size_t)(p + BHALF) * DDIM);
    float qa = 0.0f, qb = 0.0f;
    #pragma unroll
    for (int c = 0; c < 4; c++) {
        float fa[4] = { a[c].x*sa*QS, a[c].y*sa*QS, a[c].z*sa*QS, a[c].w*sa*QS };
        float fb[4] = { b[c].x*sb*QS, b[c].y*sb*QS, b[c].z*sb*QS, b[c].w*sb*QS };
        uint32_t pka = 0, pkb = 0;
        #pragma unroll
        for (int e = 0; e < 4; e++) {
            __nv_fp8_e4m3 ea(fa[e]);
            __nv_fp8_e4m3 eb(fb[e]);
            float da = float(ea), db = float(eb);
            qa += da * da;  qb += db * db;
            pka |= (uint32_t)ea.__x << (8 * e);
            pkb |= (uint32_t)eb.__x << (8 * e);
        }
        wa[l + 32 * c] = pka;
        wb[l + 32 * c] = pkb;
    }
    qa = wred(qa); qb = wred(qb);
    if (l == 0) {
        g_pos[p] = dab * sa * sb * INV_T;
        g_diag[p]         = expf(fmaf(qa, EPSC, -MSHIFT));
        g_diag[p + BHALF] = expf(fmaf(qb, EPSC, -MSHIFT));
    }
}

// ---------------------------------------------------------------------------
// Kernel 2: symmetric fp8 mma.sync GEMM, pair-major spans, 148 CTAs,
//   512 threads = 16 warps (4/SMSP) in a 4x4 warp grid of 32x32 fragments.
//   (Exact R11 mainloop, verified 135.6us.)
// ---------------------------------------------------------------------------
__global__ __launch_bounds__(NTHR, 1) void ntx_gemm_sym() {
    extern __shared__ char smraw[];
    char* sm = (char*)(((uintptr_t)smraw + 1023) & ~(uintptr_t)1023);
    const uint32_t sbase = smem_u32(sm);
    const uint32_t A0  = sbase;                       // 4 x 16KB = 64 KB
    const uint32_t Bst = sbase + 65536;               // 4 x 16KB = 64 KB
    float* red    = (float*)(sm + 131072);            // 512 floats
    float* colred = (float*)(sm + 131072 + 2048);     // 512 floats (4 wm slices)

    const int tid = threadIdx.x;
    const int l   = tid & 31;
    const int wid = tid >> 5;                // 0..15
    const int wm  = wid >> 2;                // 0..3 row quarter (32 rows)
    const int wn  = wid & 3;                 // 0..3 col quarter (32 cols)
    const int cta = blockIdx.x;
    const int u0  = (cta * NTILES) / NCTA;
    const int u1  = ((cta + 1) * NTILES) / NCTA;

    // per-lane ldmatrix bases
    const uint32_t lx    = (uint32_t)(l & 7);
    const uint32_t a_k16 = (uint32_t)(l >> 4);
    const uint32_t a_row = (uint32_t)(wm * 32 + ((l >> 3) & 1) * 8 + (l & 7));
    uint32_t a_base[2];
    #pragma unroll
    for (int mt = 0; mt < 2; mt++) a_base[mt] = A0 + (a_row + mt * 16) * 128u;
    const uint32_t b_k16 = (uint32_t)((l >> 3) & 1);
    const uint32_t b_row = (uint32_t)(wn * 32 + ((l >> 4) & 1) * 8 + (l & 7));
    uint32_t b_off[2];
    #pragma unroll
    for (int pp = 0; pp < 2; pp++) b_off[pp] = (b_row + pp * 16) * 128u;

    float acc[2][4][4];
    #pragma unroll
    for (int mt = 0; mt < 2; mt++)
        #pragma unroll
        for (int nt = 0; nt < 4; nt++)
            #pragma unroll
            for (int c = 0; c < 4; c++) acc[mt][nt][c] = 0.0f;

    int u = u0;
    while (u < u1) {
        // decode pair-major position u -> strip i, start col j0, seg end
        const int k = u / 65;
        const int v = u - k * 65;
        const int lng = NBLK - k;
        int i, j0, segend;
        if (v < lng) { i = k;            j0 = k + v;         segend = k * 65 + lng; }
        else         { i = NBLK - 1 - k; j0 = i + (v - lng); segend = (k + 1) * 65; }
        if (segend > u1) segend = u1;
        const int nch = (segend - u) * CPT;

        // drain ring, then load A tile for strip i (64KB)
        CP_WAIT0();
        __syncthreads();
        {
            const int r  = tid >> 2;             // 0..127
            const int hh = tid & 3;
            const char* src = (const char*)(g_zq + (size_t)(i * 128 + r) * DDIM);
            #pragma unroll
            for (int kc = 0; kc < CPT; kc++) {
                #pragma unroll
                for (int qq = 0; qq < 2; qq++) {
                    const int cidx = hh * 2 + qq;
                    uint32_t dst = A0 + kc * 16384u + (uint32_t)r * 128u
                                 + (uint32_t)((cidx ^ (r & 7)) << 4);
                    cpasync16(dst, src + kc * 128 + cidx * 16);
                }
            }
            CP_COMMIT();
        }

        auto loadB = [&](int c, int stage) {
            const int tj = j0 + (c >> 2);
            const int kc = c & 3;
            const int r  = tid >> 2;
            const int hh = tid & 3;
            const char* src = (const char*)
                (g_zq + (size_t)(tj * 128 + r) * DDIM) + kc * 128;
            const uint32_t db = Bst + (uint32_t)stage * 16384u + (uint32_t)r * 128u;
            #pragma unroll
            for (int qq = 0; qq < 2; qq++) {
                const int cidx = hh * 2 + qq;
                cpasync16(db + (uint32_t)((cidx ^ (r & 7)) << 4), src + cidx * 16);
            }
        };
        loadB(0, 0); CP_COMMIT();
        if (nch > 1) loadB(1, 1); CP_COMMIT();
        if (nch > 2) loadB(2, 2); CP_COMMIT();

        for (int g = 0; g < nch; g++) {
            CP_WAIT2();
            __syncthreads();
            if (g + 3 < nch) loadB(g + 3, (g + 3) & (NSTB - 1));
            CP_COMMIT();

            const int kc = g & 3;
            const uint32_t Akc = (uint32_t)kc * 16384u;
            const uint32_t Bs  = Bst + (uint32_t)(g & (NSTB - 1)) * 16384u;

            #pragma unroll
            for (int ks = 0; ks < 4; ks++) {      // 4 x k32 per 128B chunk
                const uint32_t aoffs = (((uint32_t)(ks * 2) + a_k16) ^ lx) << 4;
                const uint32_t boffs = (((uint32_t)(ks * 2) + b_k16) ^ lx) << 4;
                uint32_t a[2][4], b[2][4];
                #pragma unroll
                for (int mt = 0; mt < 2; mt++)
                    LDSM_X4(a[mt], a_base[mt] + Akc + aoffs);
                #pragma unroll
                for (int pp = 0; pp < 2; pp++)
                    LDSM_X4(b[pp], Bs + b_off[pp] + boffs);
                #pragma unroll
                for (int mt = 0; mt < 2; mt++) {
                    #pragma unroll
                    for (int pp = 0; pp < 2; pp++) {
                        MMA16832F8(acc[mt][pp*2+0], a[mt][0], a[mt][1], a[mt][2], a[mt][3],
                                   b[pp][0], b[pp][1]);
                        MMA16832F8(acc[mt][pp*2+1], a[mt][0], a[mt][1], a[mt][2], a[mt][3],
                                   b[pp][2], b[pp][3]);
                    }
                }
            }

            if (kc == CPT - 1) {
                const int j  = j0 + (g >> 2);
                const int tl = tile_index(i, j);
                float rac[2][2], cs[4][2];
                #pragma unroll
                for (int x = 0; x < 2; x++) { rac[x][0] = 0.0f; rac[x][1] = 0.0f; }
                #pragma unroll
                for (int x = 0; x < 4; x++) { cs[x][0] = 0.0f;  cs[x][1] = 0.0f; }
                #pragma unroll
                for (int mt = 0; mt < 2; mt++) {
                    #pragma unroll
                    for (int nt = 0; nt < 4; nt++) {
                        float e0 = __expf(fmaf(acc[mt][nt][0], EPSC, -MSHIFT));
                        float e1 = __expf(fmaf(acc[mt][nt][1], EPSC, -MSHIFT));
                        float e2 = __expf(fmaf(acc[mt][nt][2], EPSC, -MSHIFT));
                        float e3 = __expf(fmaf(acc[mt][nt][3], EPSC, -MSHIFT));
                        rac[mt][0] += e0 + e1;
                        rac[mt][1] += e2 + e3;
                        cs[nt][0]  += e0 + e2;
                        cs[nt][1]  += e1 + e3;
                        acc[mt][nt][0] = 0.0f; acc[mt][nt][1] = 0.0f;
                        acc[mt][nt][2] = 0.0f; acc[mt][nt][3] = 0.0f;
                    }
                }
                // row reduce: lanes sharing a row (strides 1,2)
                #pragma unroll
                for (int mt = 0; mt < 2; mt++) {
                    #pragma unroll
                    for (int h = 0; h < 2; h++) {
                        float vv = rac[mt][h];
                        vv += __shfl_xor_sync(0xffffffffu, vv, 1);
                        vv += __shfl_xor_sync(0xffffffffu, vv, 2);
                        if ((l & 3) == 0) {
                            const int row_local = wm * 32 + mt * 16 + (l >> 2) + 8 * h;
                            red[row_local * 4 + wn] = vv;
                        }
                    }
                }
                // col reduce across 8 row-lane groups (strides 4,8,16)
                #pragma unroll
                for (int off = 4; off <= 16; off <<= 1)
                    #pragma unroll
                    for (int nt = 0; nt < 4; nt++) {
                        cs[nt][0] += __shfl_xor_sync(0xffffffffu, cs[nt][0], off);
                        cs[nt][1] += __shfl_xor_sync(0xffffffffu, cs[nt][1], off);
                    }
                if (l < 4) {
                    #pragma unroll
                    for (int nt = 0; nt < 4; nt++) {
                        const int colb = wn * 32 + (nt >> 1) * 16 + (nt & 1) * 8 + 2 * l;
                        colred[wm * 128 + colb    ] = cs[nt][0];
                        colred[wm * 128 + colb + 1] = cs[nt][1];
                    }
                }
                __syncthreads();
                if (tid < 128) {
                    g_rowtile[(size_t)tl * 128 + tid] =
                        red[tid*4+0] + red[tid*4+1] + red[tid*4+2] + red[tid*4+3];
                    if (j > i)
                        g_coltile[(size_t)tl * 128 + tid] =
                            colred[tid] + colred[128 + tid] +
                            colred[256 + tid] + colred[384 + tid];
                }
            }
        }
        u = segend;
    }
}

// ---------------------------------------------------------------------------
// Kernel 3: combine per-tile partials -> per-row loss.
// ---------------------------------------------------------------------------
__global__ void ntx_rowsum_loss() {
    const int b  = blockIdx.x;
    const int rl = threadIdx.x;
    const int r  = b * 128 + rl;
    const int base_b = b * (129 - b) / 2;
    float s = 0.0f;
    for (int j = b; j < NBLK; j++)
        s += g_rowtile[(size_t)(base_b + (j - b)) * 128 + rl];
    for (int i = 0; i < b; i++)
        s += g_coltile[(size_t)(i * (129 - i) / 2 + (b - i)) * 128 + rl];
    const float pos = g_pos[r & (BHALF - 1)];
    g_rowloss[r] = MSHIFT + logf(s - g_diag[r]) - pos;
}

// ---------------------------------------------------------------------------
// Kernel 4: mean over NROWS -> scalar out.
// ---------------------------------------------------------------------------
__global__ void ntx_reduce(float* __restrict__ out) {
    const int t = threadIdx.x;               // 1024 threads
    float s = 0.0f;
    #pragma unroll
    for (int k = 0; k < NROWS / 1024; k++) s += g_rowloss[t + k * 1024];
    #pragma unroll
    for (int o = 16; o > 0; o >>= 1) s += __shfl_xor_sync(0xffffffffu, s, o);
    __shared__ float sw[32];
    if ((t & 31) == 0) sw[t >> 5] = s;
    __syncthreads();
    if (t == 0) {
        float tot = 0.0f;
        #pragma unroll
        for (int w = 0; w < 32; w++) tot += sw[w];
        out[0] = tot * (1.0f / (float)NROWS);
    }
}

// ---------------------------------------------------------------------------
#define SMEM_BYTES (1024 + 65536 + 65536 + 2048 + 2048)

extern "C" void kernel_launch(void* const* d_in, const int* in_sizes, int n_in,
                              void* d_out, int out_size) {
    const float* zi = (const float*)d_in[0];
    const float* zj = (const float*)d_in[1];
    float* out = (float*)d_out;
    (void)in_sizes; (void)n_in; (void)out_size;

    cudaFuncSetAttribute(ntx_gemm_sym,
                         cudaFuncAttributeMaxDynamicSharedMemorySize, SMEM_BYTES);

    ntx_norm_pair<<<512, 256>>>(zi, zj);
    ntx_gemm_sym<<<NCTA, NTHR, SMEM_BYTES>>>();
    ntx_rowsum_loss<<<NBLK, 128>>>();
    ntx_reduce<<<1, 1024>>>(out);
}